// round 7
// baseline (speedup 1.0000x reference)
#include <cuda_runtime.h>

// Grad3D: out = |dx| + |dy| + |dz| with central differences, zero-padded.
// x shape (4, 1, 192, 224, 192) fp32, contiguous.
// Register D-march, 2 planes per barrier: each thread owns one (h, w4) quad.
// z-derivative & center live in registers; smem (4 rotating plane slots) serves
// lf/rt/up/dn neighbor reads. One __syncthreads per 2 planes.

#define Nn 4
#define Dd 192
#define Hh 224
#define Ww 192
#define HW (Hh * Ww)          // 43008
#define DHW (Dd * HW)         // 8257536

#define BH 8                  // H output rows per block
#define DCHUNK 16             // D planes per block
#define NROWS (BH + 2)        // incl. halo rows (10)
#define ROWSTRIDE 200         // floats/row (800B): [3]=zero(w=-1), [4..195]=data, [196]=zero(w=192)
#define NBUF 4
#define QPERROW (Ww / 4)      // 48
#define THREADS (NROWS * QPERROW)  // 480

__global__ void __launch_bounds__(THREADS, 3)
grad3d_kernel(const float* __restrict__ x, float* __restrict__ out)
{
    __shared__ __align__(16) float sm[NBUF][NROWS * ROWSTRIDE];

    const int tid  = threadIdx.x;
    const int r    = tid / QPERROW;       // 0..9 (r=0, r=9 are halo rows)
    const int q    = tid - r * QPERROW;   // 0..47
    const int h0   = blockIdx.x * BH;     // 0..216
    const int d0   = blockIdx.y * DCHUNK; // 0..176
    const int dend = d0 + DCHUNK;
    const int n    = blockIdx.z;
    const int gh   = h0 - 1 + r;
    const bool inH  = (gh >= 0) && (gh < Hh);
    const bool comp = (r >= 1) && (r <= BH);

    // Zero guard columns (w=-1 at [3], w=W at [196]) in all 4 slots.
    if (q < NBUF * 2) {  // threads q=0..7 of each row handle (slot, side)
        int b    = q >> 1;
        int side = q & 1;
        sm[b][r * ROWSTRIDE + (side ? (4 + Ww) : 3)] = 0.0f;
    }

    const float* __restrict__ src =
        x + (size_t)n * DHW + (size_t)(inH ? gh : 0) * Ww + q * 4;
    float* __restrict__ dst =
        out + (size_t)n * DHW + (size_t)(comp ? gh : 0) * Ww + q * 4;

    const int soff = r * ROWSTRIDE + 4 + q * 4;

    auto ldq = [&](int d) -> float4 {
        if (inH && (unsigned)d < (unsigned)Dd)
            return *reinterpret_cast<const float4*>(src + (size_t)d * HW);
        return make_float4(0.f, 0.f, 0.f, 0.f);
    };

    // One-plane gradient from regs (prev/center/next quads) + smem slot for lf/rt/up/dn.
    auto do_plane = [&](int d, const float* slot, float4 pv, float4 cc, float4 nx) {
        const float* cb = slot + soff;
        float  lf = cb[-1];                                          // guard at q==0
        float  rt = cb[4];                                           // guard at q==47
        float4 up = *reinterpret_cast<const float4*>(cb - ROWSTRIDE);
        float4 dn = *reinterpret_cast<const float4*>(cb + ROWSTRIDE);
        float4 o;
        o.x = 0.5f * (fabsf(cc.y - lf)   + fabsf(dn.x - up.x) + fabsf(nx.x - pv.x));
        o.y = 0.5f * (fabsf(cc.z - cc.x) + fabsf(dn.y - up.y) + fabsf(nx.y - pv.y));
        o.z = 0.5f * (fabsf(cc.w - cc.y) + fabsf(dn.z - up.z) + fabsf(nx.z - pv.z));
        o.w = 0.5f * (fabsf(rt   - cc.z) + fabsf(dn.w - up.w) + fabsf(nx.w - pv.w));
        *reinterpret_cast<float4*>(dst + (size_t)d * HW) = o;
    };

    // Invariant entering iter d: regs p0=x[d-1], c0=x[d], n0=x[d+1], n1=x[d+2];
    // sm[d&3]=plane d, sm[(d+1)&3]=plane d+1.
    float4 p0 = ldq(d0 - 1);
    float4 c0 = ldq(d0);
    float4 n0 = ldq(d0 + 1);
    float4 n1 = ldq(d0 + 2);
    *reinterpret_cast<float4*>(&sm[d0 & 3][soff])       = c0;
    *reinterpret_cast<float4*>(&sm[(d0 + 1) & 3][soff]) = n0;
    __syncthreads();

    for (int d = d0; d < dend; d += 2) {
        const bool more = (d + 2 < dend);   // block-uniform

        // Prefetch the two planes needed two iterations ahead (MLP=2).
        float4 t0 = more ? ldq(d + 3) : make_float4(0.f, 0.f, 0.f, 0.f);
        float4 t1 = more ? ldq(d + 4) : make_float4(0.f, 0.f, 0.f, 0.f);

        if (comp) {
            do_plane(d,     sm[d & 3],       p0, c0, n0);   // z: x[d+1]-x[d-1]
            do_plane(d + 1, sm[(d + 1) & 3], c0, n0, n1);   // z: x[d+2]-x[d]
        }

        if (more) {
            // Publish planes d+2 and d+3 into the two slots not read this iter.
            *reinterpret_cast<float4*>(&sm[(d + 2) & 3][soff]) = n1;
            *reinterpret_cast<float4*>(&sm[(d + 3) & 3][soff]) = t0;
            __syncthreads();
        }

        p0 = n0; c0 = n1; n0 = t0; n1 = t1;
    }
}

extern "C" void kernel_launch(void* const* d_in, const int* in_sizes, int n_in,
                              void* d_out, int out_size)
{
    const float* x = (const float*)d_in[0];
    float* out = (float*)d_out;
    dim3 grid(Hh / BH, Dd / DCHUNK, Nn);   // 28 x 12 x 4 = 1344 blocks
    grad3d_kernel<<<grid, THREADS>>>(x, out);
}